// round 6
// baseline (speedup 1.0000x reference)
#include <cuda_runtime.h>
#include <math.h>

#define TILE 32
#define IMG_H 512
#define IMG_W 512
#define NTHREADS 256

typedef unsigned long long ull;

__device__ double g_acc;

__global__ void init_acc_kernel() { g_acc = 0.0; }

__global__ void finalize_kernel(float* out, double scale) {
    out[0] = (float)(g_acc * scale);
}

// ---- f32x2 packed helpers ----
__device__ __forceinline__ ull pack2(float lo, float hi) {
    ull r;
    asm("mov.b64 %0, {%1, %2};" : "=l"(r) : "f"(lo), "f"(hi));
    return r;
}
__device__ __forceinline__ void unpack2(ull v, float& lo, float& hi) {
    asm("mov.b64 {%0, %1}, %2;" : "=f"(lo), "=f"(hi) : "l"(v));
}
__device__ __forceinline__ void ffma2(ull& d, ull a, ull b) {
    asm("fma.rn.f32x2 %0, %1, %2, %0;" : "+l"(d) : "l"(a), "l"(b));
}
__device__ __forceinline__ ull fma2v(ull a, ull b, ull c) {   // a*b + c
    ull d;
    asm("fma.rn.f32x2 %0, %1, %2, %3;" : "=l"(d) : "l"(a), "l"(b), "l"(c));
    return d;
}
__device__ __forceinline__ ull mul2(ull a, ull b) {
    ull d;
    asm("mul.rn.f32x2 %0, %1, %2;" : "=l"(d) : "l"(a), "l"(b));
    return d;
}

// ---- shared memory layout (bytes) ----
// hb: 46 rows x 39 u128  (level-1 horizontal conv; union with h2: MS x 33 u128)
// ms: MS rows x 39 u64   (packed means)
// vs: 32 rows x 33 u64   (packed clipped variances, inner pixels)
#define HB_BYTES (46 * 39 * 16)
__host__ __device__ constexpr int ms_bytes(int K) {
    return (TILE + 2 * (K / 2)) * 39 * 8;
}
__host__ __device__ constexpr int smem_total(int K) {
    return HB_BYTES + ms_bytes(K) + 32 * 33 * 8;
}

template <int K>
__global__ __launch_bounds__(NTHREADS, 4)
void stat_loss_kernel(const float* __restrict__ pred,
                      const float* __restrict__ tgt)
{
    constexpr int R    = K / 2;
    constexpr int XS   = TILE + 4 * R;    // level-1 row span
    constexpr int MS   = TILE + 2 * R;    // mean-field side
    constexpr int HBW  = 39;              // hb row stride (u128)
    constexpr int MSW  = 39;              // ms row stride (u64)
    constexpr int H2W  = 33;              // h2 row stride (u128)
    constexpr int VSW  = 33;              // vs row stride (u64)
    constexpr int QH   = 8 + K - 1;       // taps per 8-wide horizontal group
    constexpr int QV8  = 8 + K - 1;       // taps per 8-row vertical group
    constexpr int QV4  = 4 + K - 1;       // taps per 4-row vertical group

    extern __shared__ __align__(16) unsigned char smem[];
    __shared__ float wsum[NTHREADS / 32];

    ulonglong2* hb = (ulonglong2*)smem;                        // S2->S3
    ulonglong2* h2 = (ulonglong2*)smem;                        // S4->S5 (aliases hb)
    ull*        ms = (ull*)(smem + HB_BYTES);                  // mean pairs
    ull*        vs = (ull*)(smem + HB_BYTES + ms_bytes(K));    // var pairs

    const int tid = threadIdx.x;
    const int x0 = blockIdx.x * TILE;
    const int y0 = blockIdx.y * TILE;
    const size_t plane_off = (size_t)blockIdx.z * (size_t)(IMG_H * IMG_W);

    // normalized 1D gaussian, packed
    ull gp[K];
    {
        const float sigma = (float)K / 6.0f;
        const float inv2s2 = 1.0f / (2.0f * sigma * sigma);
        float gtmp[K];
        float s = 0.0f;
#pragma unroll
        for (int j = 0; j < K; ++j) {
            float c = (float)(j - K / 2);
            gtmp[j] = expf(-c * c * inv2s2);
            s += gtmp[j];
        }
        float inv = 1.0f / s;
#pragma unroll
        for (int j = 0; j < K; ++j) { float w = gtmp[j] * inv; gp[j] = pack2(w, w); }
    }
    const ull NEG1 = pack2(-1.0f, -1.0f);

    const bool edge = (x0 < 2 * R) || (y0 < 2 * R) ||
                      (x0 + TILE + 2 * R > IMG_W) || (y0 + TILE + 2 * R > IMG_H);

    // stage mappings (single shot)
    const int s2_row = tid / 5, s2_cx = (tid % 5) * 8;    // XS rows × 5 groups
    const int s3_c = tid % MS, s3_r0 = (tid / MS) * 8;    // MS cols × 5 groups
    const int s4_row = tid >> 2, s4_cx = (tid & 3) * 8;   // MS rows × 4 groups
    const int ocx = tid & 31, org = (tid >> 5) * 4;       // 32 cols × 8 groups

    const float* srcp = pred + plane_off;
    const float* srct = tgt + plane_off;

    float acc = 0.0f;

    // ---- S2: horizontal conv of (x, x^2); x taps read straight from global ----
    if (tid < XS * 5) {
        ull a1[8], a2[8];
#pragma unroll
        for (int rr = 0; rr < 8; ++rr) { a1[rr] = 0ull; a2[rr] = 0ull; }
        const int gy  = y0 - 2 * R + s2_row;
        const int gxb = x0 - 2 * R + s2_cx;
        if (!edge) {
            const float* rp = srcp + (size_t)gy * IMG_W + gxb;
            const float* rt = srct + (size_t)gy * IMG_W + gxb;
#pragma unroll
            for (int q = 0; q < QH; ++q) {
                ull xp = pack2(rp[q], rt[q]);
                ull x2 = mul2(xp, xp);
#pragma unroll
                for (int rr = 0; rr < 8; ++rr) {
                    int j = q - rr;
                    if (j >= 0 && j < K) { ffma2(a1[rr], gp[j], xp); ffma2(a2[rr], gp[j], x2); }
                }
            }
        } else {
            const bool rowin = (unsigned)gy < (unsigned)IMG_H;
#pragma unroll
            for (int q = 0; q < QH; ++q) {
                int gx = gxb + q;
                bool in = rowin && ((unsigned)gx < (unsigned)IMG_W);
                float vp = in ? srcp[(size_t)gy * IMG_W + gx] : 0.0f;
                float vt = in ? srct[(size_t)gy * IMG_W + gx] : 0.0f;
                ull xp = pack2(vp, vt);
                ull x2 = mul2(xp, xp);
#pragma unroll
                for (int rr = 0; rr < 8; ++rr) {
                    int j = q - rr;
                    if (j >= 0 && j < K) { ffma2(a1[rr], gp[j], xp); ffma2(a2[rr], gp[j], x2); }
                }
            }
        }
        ulonglong2* hrow = hb + s2_row * HBW;
#pragma unroll
        for (int rr = 0; rr < 8; ++rr) {
            if (s2_cx + rr < MS) {
                ulonglong2 o; o.x = a1[rr]; o.y = a2[rr];
                hrow[s2_cx + rr] = o;
            }
        }
    }
    __syncthreads();

    // ---- S3: vertical conv -> mean pairs (ms) + clipped variance pairs (vs) ----
    if (tid < MS * 5) {
        const ulonglong2* hcol = hb + s3_r0 * HBW + s3_c;
        ull a1[8], a2[8];
#pragma unroll
        for (int rr = 0; rr < 8; ++rr) { a1[rr] = 0ull; a2[rr] = 0ull; }
#pragma unroll
        for (int q = 0; q < QV8; ++q) {
            ulonglong2 p = hcol[q * HBW];
#pragma unroll
            for (int rr = 0; rr < 8; ++rr) {
                int j = q - rr;
                if (j >= 0 && j < K) { ffma2(a1[rr], gp[j], p.x); ffma2(a2[rr], gp[j], p.y); }
            }
        }
#pragma unroll
        for (int rr = 0; rr < 8; ++rr) {
            int row = s3_r0 + rr;
            if (row < MS) {
                ms[row * MSW + s3_c] = a1[rr];
                int vy = row - R, vx = s3_c - R;
                if ((unsigned)vy < 32u && (unsigned)vx < 32u) {
                    float mp, mt, sp, st;
                    unpack2(a1[rr], mp, mt);
                    unpack2(a2[rr], sp, st);
                    float vpv = fmaxf(sp - mp * mp, 1e-8f);
                    float vtv = fmaxf(st - mt * mt, 1e-8f);
                    vs[vy * VSW + vx] = pack2(vpv, vtv);
                }
            }
        }
    }
    __syncthreads();

    // ---- S4 (fused): horizontal conv of (xc^3, xc^4); x taps from global ----
    if (tid < MS * 4) {
        const ull* mrow = ms + s4_row * MSW + s4_cx;
        ull a3[8], a4[8];
#pragma unroll
        for (int rr = 0; rr < 8; ++rr) { a3[rr] = 0ull; a4[rr] = 0ull; }
        const int gy  = y0 - R + s4_row;
        const int gxb = x0 - R + s4_cx;
        if (!edge) {
            const float* rp = srcp + (size_t)gy * IMG_W + gxb;
            const float* rt = srct + (size_t)gy * IMG_W + gxb;
#pragma unroll
            for (int q = 0; q < QH; ++q) {
                ull xp  = pack2(rp[q], rt[q]);
                ull xc  = fma2v(mrow[q], NEG1, xp);     // x - mean
                ull xc2 = mul2(xc, xc);
                ull c3  = mul2(xc2, xc);
                ull c4  = mul2(xc2, xc2);
#pragma unroll
                for (int rr = 0; rr < 8; ++rr) {
                    int j = q - rr;
                    if (j >= 0 && j < K) { ffma2(a3[rr], gp[j], c3); ffma2(a4[rr], gp[j], c4); }
                }
            }
        } else {
            const bool rowin = (unsigned)gy < (unsigned)IMG_H;
#pragma unroll
            for (int q = 0; q < QH; ++q) {
                int gx = gxb + q;
                bool in = rowin && ((unsigned)gx < (unsigned)IMG_W);
                float vp = in ? srcp[(size_t)gy * IMG_W + gx] : 0.0f;
                float vt = in ? srct[(size_t)gy * IMG_W + gx] : 0.0f;
                ull xp  = pack2(vp, vt);
                ull xc  = fma2v(mrow[q], NEG1, xp);
                ull xc2 = mul2(xc, xc);
                ull c3  = in ? mul2(xc2, xc)  : 0ull;
                ull c4  = in ? mul2(xc2, xc2) : 0ull;
#pragma unroll
                for (int rr = 0; rr < 8; ++rr) {
                    int j = q - rr;
                    if (j >= 0 && j < K) { ffma2(a3[rr], gp[j], c3); ffma2(a4[rr], gp[j], c4); }
                }
            }
        }
        ulonglong2* orow = h2 + s4_row * H2W + s4_cx;
#pragma unroll
        for (int rr = 0; rr < 8; ++rr) {
            ulonglong2 o; o.x = a3[rr]; o.y = a4[rr];
            orow[rr] = o;
        }
    }
    __syncthreads();

    // ---- S5: vertical conv -> (m3, m4); features + loss for both tensors ----
    {
        const ulonglong2* hcol = h2 + org * H2W + ocx;
        ull a3[4], a4[4];
#pragma unroll
        for (int rr = 0; rr < 4; ++rr) { a3[rr] = 0ull; a4[rr] = 0ull; }
#pragma unroll
        for (int q = 0; q < QV4; ++q) {
            ulonglong2 p = hcol[q * H2W];
#pragma unroll
            for (int rr = 0; rr < 4; ++rr) {
                int j = q - rr;
                if (j >= 0 && j < K) { ffma2(a3[rr], gp[j], p.x); ffma2(a4[rr], gp[j], p.y); }
            }
        }
#pragma unroll
        for (int rr = 0; rr < 4; ++rr) {
            float m3p, m3t, m4p, m4t;
            unpack2(a3[rr], m3p, m3t);
            unpack2(a4[rr], m4p, m4t);
            float mp, mt, vp, vt;
            unpack2(ms[(org + rr + R) * MSW + (ocx + R)], mp, mt);
            unpack2(vs[(org + rr) * VSW + ocx], vp, vt);
            float sdp = sqrtf(vp), sdt = sqrtf(vt);
            float skp = __fdividef(m3p, sdp * sdp * sdp + 1e-8f);
            float skt = __fdividef(m3t, sdt * sdt * sdt + 1e-8f);
            float kup = __fdividef(m4p, vp * vp + 1e-8f);
            float kut = __fdividef(m4t, vt * vt + 1e-8f);
            acc += fabsf(mp - mt)
                 + fabsf(vp - vt)
                 + 0.5f   * fabsf(skp - skt)
                 + 0.001f * fabsf(kup - kut);
        }
    }

    // ---- block reduction, atomic accumulate ----
#pragma unroll
    for (int off = 16; off > 0; off >>= 1)
        acc += __shfl_xor_sync(0xffffffffu, acc, off);
    if ((tid & 31) == 0) wsum[tid >> 5] = acc;
    __syncthreads();
    if (tid < 32) {
        float v = (tid < NTHREADS / 32) ? wsum[tid] : 0.0f;
#pragma unroll
        for (int off = 16; off > 0; off >>= 1)
            v += __shfl_xor_sync(0xffffffffu, v, off);
        if (tid == 0) atomicAdd(&g_acc, (double)v);
    }
}

extern "C" void kernel_launch(void* const* d_in, const int* in_sizes, int n_in,
                              void* d_out, int out_size) {
    const float* pred = (const float*)d_in[0];
    const float* tgt  = (const float*)d_in[1];
    float* out = (float*)d_out;

    const int npix = in_sizes[0];                 // 16*3*512*512
    const int planes = npix / (IMG_H * IMG_W);    // 48

    dim3 grid(IMG_W / TILE, IMG_H / TILE, planes);

    cudaFuncSetAttribute(stat_loss_kernel<3>, cudaFuncAttributeMaxDynamicSharedMemorySize,
                         smem_total(3));
    cudaFuncSetAttribute(stat_loss_kernel<5>, cudaFuncAttributeMaxDynamicSharedMemorySize,
                         smem_total(5));
    cudaFuncSetAttribute(stat_loss_kernel<7>, cudaFuncAttributeMaxDynamicSharedMemorySize,
                         smem_total(7));

    init_acc_kernel<<<1, 1>>>();
    stat_loss_kernel<3><<<grid, NTHREADS, smem_total(3)>>>(pred, tgt);
    stat_loss_kernel<5><<<grid, NTHREADS, smem_total(5)>>>(pred, tgt);
    stat_loss_kernel<7><<<grid, NTHREADS, smem_total(7)>>>(pred, tgt);

    const double scale = 1.0 / (12.0 * (double)npix);
    finalize_kernel<<<1, 1>>>(out, scale);
}

// round 7
// speedup vs baseline: 1.0630x; 1.0630x over previous
#include <cuda_runtime.h>
#include <math.h>

#define TILE 32
#define IMG_H 512
#define IMG_W 512
#define NTHREADS 256

typedef unsigned long long ull;

__device__ double g_acc;

__global__ void init_acc_kernel() { g_acc = 0.0; }

__global__ void finalize_kernel(float* out, double scale) {
    out[0] = (float)(g_acc * scale);
}

// ---- f32x2 packed helpers ----
__device__ __forceinline__ ull pack2(float lo, float hi) {
    ull r;
    asm("mov.b64 %0, {%1, %2};" : "=l"(r) : "f"(lo), "f"(hi));
    return r;
}
__device__ __forceinline__ void unpack2(ull v, float& lo, float& hi) {
    asm("mov.b64 {%0, %1}, %2;" : "=f"(lo), "=f"(hi) : "l"(v));
}
__device__ __forceinline__ void ffma2(ull& d, ull a, ull b) {
    asm("fma.rn.f32x2 %0, %1, %2, %0;" : "+l"(d) : "l"(a), "l"(b));
}
__device__ __forceinline__ ull fma2v(ull a, ull b, ull c) {   // a*b + c
    ull d;
    asm("fma.rn.f32x2 %0, %1, %2, %3;" : "=l"(d) : "l"(a), "l"(b), "l"(c));
    return d;
}
__device__ __forceinline__ ull mul2(ull a, ull b) {
    ull d;
    asm("mul.rn.f32x2 %0, %1, %2;" : "=l"(d) : "l"(a), "l"(b));
    return d;
}

// ---- smem layout (bytes), all 16B aligned ----
// xs : XS x XS u64 (packed pred/tgt), stride XS
// B  : union{ hb: XS x (MS+1) u64 ; h2: MS x 32 u128 }
// ms : MS x MS u64 (packed means), stride MS
// hb2: MS x 32 u64 (packed hconv of x^2, inner cols), stride 32
__host__ __device__ constexpr int c_XS(int K) { return TILE + 4 * (K / 2); }
__host__ __device__ constexpr int c_MS(int K) { return TILE + 2 * (K / 2); }
__host__ __device__ constexpr int xs_bytes(int K) { return c_XS(K) * c_XS(K) * 8; }
__host__ __device__ constexpr int b_bytes(int K) {
    int hb = c_XS(K) * (c_MS(K) + 1) * 8;
    int h2 = c_MS(K) * 32 * 16;
    return hb > h2 ? hb : h2;
}
__host__ __device__ constexpr int ms_bytes(int K) { return c_MS(K) * c_MS(K) * 8; }
__host__ __device__ constexpr int hb2_bytes(int K) { return c_MS(K) * 32 * 8; }
__host__ __device__ constexpr int smem_total(int K) {
    return xs_bytes(K) + b_bytes(K) + ms_bytes(K) + hb2_bytes(K);
}

template <int K>
__global__ __launch_bounds__(NTHREADS, 4)
void stat_loss_kernel(const float* __restrict__ pred,
                      const float* __restrict__ tgt)
{
    constexpr int R    = K / 2;
    constexpr int XS   = TILE + 4 * R;
    constexpr int MS   = TILE + 2 * R;
    constexpr int XSP  = XS;          // xs row stride (u64)
    constexpr int HBW  = MS + 1;      // hb row stride (u64)
    constexpr int MSW  = MS;          // ms row stride (u64)
    constexpr int H2W  = 32;          // h2 row stride (u128)
    constexpr int HB2W = 32;          // hb2 row stride (u64)
    constexpr int QH   = 8 + K - 1;   // taps per 8-wide horizontal group
    constexpr int QH16 = 16 + K - 1;  // taps per 16-wide group (S2b)
    constexpr int QV8  = 8 + K - 1;
    constexpr int QV4  = 4 + K - 1;

    extern __shared__ __align__(16) unsigned char smem[];
    __shared__ float wsum[NTHREADS / 32];

    ull*        xs  = (ull*)smem;
    ull*        hb  = (ull*)(smem + xs_bytes(K));                 // S2a->S3a
    ulonglong2* h2  = (ulonglong2*)(smem + xs_bytes(K));          // S4->S5 (aliases hb)
    ull*        ms  = (ull*)(smem + xs_bytes(K) + b_bytes(K));
    ull*        hb2 = (ull*)(smem + xs_bytes(K) + b_bytes(K) + ms_bytes(K));

    const int tid = threadIdx.x;
    const int x0 = blockIdx.x * TILE;
    const int y0 = blockIdx.y * TILE;
    const size_t plane_off = (size_t)blockIdx.z * (size_t)(IMG_H * IMG_W);

    // normalized 1D gaussian, packed
    ull gp[K];
    {
        const float sigma = (float)K / 6.0f;
        const float inv2s2 = 1.0f / (2.0f * sigma * sigma);
        float gtmp[K];
        float s = 0.0f;
#pragma unroll
        for (int j = 0; j < K; ++j) {
            float c = (float)(j - K / 2);
            gtmp[j] = expf(-c * c * inv2s2);
            s += gtmp[j];
        }
        float inv = 1.0f / s;
#pragma unroll
        for (int j = 0; j < K; ++j) { float w = gtmp[j] * inv; gp[j] = pack2(w, w); }
    }
    const ull NEG1 = pack2(-1.0f, -1.0f);

    const bool edge = (x0 < 2 * R) || (y0 < 2 * R) ||
                      (x0 + TILE + 2 * R > IMG_W) || (y0 + TILE + 2 * R > IMG_H);

    const float* srcp = pred + plane_off;
    const float* srct = tgt + plane_off;

    float acc = 0.0f;

    // ---- S1: load packed (pred, tgt) tile with halo 2R, zero outside ----
    if (!edge) {
        const float* bp = srcp + (size_t)(y0 - 2 * R) * IMG_W + (x0 - 2 * R);
        const float* bt = srct + (size_t)(y0 - 2 * R) * IMG_W + (x0 - 2 * R);
        for (int idx = tid; idx < XS * XS; idx += NTHREADS) {
            int ry = idx / XS, rx = idx - ry * XS;
            xs[ry * XSP + rx] = pack2(bp[ry * IMG_W + rx], bt[ry * IMG_W + rx]);
        }
    } else {
        for (int idx = tid; idx < XS * XS; idx += NTHREADS) {
            int ry = idx / XS, rx = idx - ry * XS;
            int gy = y0 - 2 * R + ry, gx = x0 - 2 * R + rx;
            ull v = 0ull;
            if ((unsigned)gy < (unsigned)IMG_H && (unsigned)gx < (unsigned)IMG_W)
                v = pack2(srcp[gy * IMG_W + gx], srct[gy * IMG_W + gx]);
            xs[ry * XSP + rx] = v;
        }
    }
    __syncthreads();

    // ---- S2a: horizontal conv of x -> hb (XS rows x MS cols) ----
    if (tid < XS * 5) {
        const int row = tid / 5, cx = (tid % 5) * 8;
        const ull* xrow = xs + row * XSP + cx;
        ull a1[8];
#pragma unroll
        for (int rr = 0; rr < 8; ++rr) a1[rr] = 0ull;
#pragma unroll
        for (int q = 0; q < QH; ++q) {
            ull xp = xrow[q];
#pragma unroll
            for (int rr = 0; rr < 8; ++rr) {
                int j = q - rr;
                if (j >= 0 && j < K) ffma2(a1[rr], gp[j], xp);
            }
        }
        ull* hrow = hb + row * HBW;
#pragma unroll
        for (int rr = 0; rr < 8; ++rr)
            if (cx + rr < MS) hrow[cx + rr] = a1[rr];
    }
    __syncthreads();

    // ---- S3a: vertical conv of hb -> ms (mean pairs, MS x MS) ----
    if (tid < MS * 5) {
        const int col = tid % MS, r0 = (tid / MS) * 8;
        const ull* hcol = hb + r0 * HBW + col;
        ull a1[8];
#pragma unroll
        for (int rr = 0; rr < 8; ++rr) a1[rr] = 0ull;
#pragma unroll
        for (int q = 0; q < QV8; ++q) {
            ull p = hcol[q * HBW];
#pragma unroll
            for (int rr = 0; rr < 8; ++rr) {
                int j = q - rr;
                if (j >= 0 && j < K) ffma2(a1[rr], gp[j], p);
            }
        }
#pragma unroll
        for (int rr = 0; rr < 8; ++rr)
            if (r0 + rr < MS) ms[(r0 + rr) * MSW + col] = a1[rr];
    }
    __syncthreads();

    // ---- S4 (152 thr): hconv of (xc^3, xc^4) -> h2   ∥
    //      S2b (76 thr): hconv of x^2 (inner 32 cols) -> hb2 ----
    if (tid < MS * 4) {
        const int row = tid >> 2, cx = (tid & 3) * 8;
        const ull* xrow = xs + (row + R) * XSP + (cx + R);
        const ull* mrow = ms + row * MSW + cx;
        ull a3[8], a4[8];
#pragma unroll
        for (int rr = 0; rr < 8; ++rr) { a3[rr] = 0ull; a4[rr] = 0ull; }
        if (!edge) {
#pragma unroll
            for (int q = 0; q < QH; ++q) {
                ull xc  = fma2v(mrow[q], NEG1, xrow[q]);   // x - mean
                ull xc2 = mul2(xc, xc);
                ull c3  = mul2(xc2, xc);
                ull c4  = mul2(xc2, xc2);
#pragma unroll
                for (int rr = 0; rr < 8; ++rr) {
                    int j = q - rr;
                    if (j >= 0 && j < K) { ffma2(a3[rr], gp[j], c3); ffma2(a4[rr], gp[j], c4); }
                }
            }
        } else {
            const int gy = y0 - R + row;
            const bool rowin = (unsigned)gy < (unsigned)IMG_H;
#pragma unroll
            for (int q = 0; q < QH; ++q) {
                int gx = x0 - R + cx + q;
                bool in = rowin && ((unsigned)gx < (unsigned)IMG_W);
                ull xc  = fma2v(mrow[q], NEG1, xrow[q]);
                ull xc2 = mul2(xc, xc);
                ull c3  = in ? mul2(xc2, xc)  : 0ull;
                ull c4  = in ? mul2(xc2, xc2) : 0ull;
#pragma unroll
                for (int rr = 0; rr < 8; ++rr) {
                    int j = q - rr;
                    if (j >= 0 && j < K) { ffma2(a3[rr], gp[j], c3); ffma2(a4[rr], gp[j], c4); }
                }
            }
        }
        ulonglong2* orow = h2 + row * H2W + cx;
#pragma unroll
        for (int rr = 0; rr < 8; ++rr) {
            ulonglong2 o; o.x = a3[rr]; o.y = a4[rr];
            orow[rr] = o;
        }
    } else if (tid < MS * 4 + MS * 2) {
        const int u = tid - MS * 4;
        const int row = u >> 1, cx = (u & 1) * 16;        // 16-wide groups
        const ull* xrow = xs + (row + R) * XSP + (cx + R);
        ull a2[16];
#pragma unroll
        for (int rr = 0; rr < 16; ++rr) a2[rr] = 0ull;
#pragma unroll
        for (int q = 0; q < QH16; ++q) {
            ull xp = xrow[q];
            ull x2 = mul2(xp, xp);
#pragma unroll
            for (int rr = 0; rr < 16; ++rr) {
                int j = q - rr;
                if (j >= 0 && j < K) ffma2(a2[rr], gp[j], x2);
            }
        }
        ull* orow = hb2 + row * HB2W + cx;
#pragma unroll
        for (int rr = 0; rr < 16; ++rr) orow[rr] = a2[rr];
    }
    __syncthreads();

    // ---- S5: vertical convs of (m3,m4) and S2; features + loss ----
    {
        const int ocx = tid & 31, org = (tid >> 5) * 4;
        const ulonglong2* hcol = h2 + org * H2W + ocx;
        const ull* vcol = hb2 + org * HB2W + ocx;
        ull a3[4], a4[4], a2[4];
#pragma unroll
        for (int rr = 0; rr < 4; ++rr) { a3[rr] = 0ull; a4[rr] = 0ull; a2[rr] = 0ull; }
#pragma unroll
        for (int q = 0; q < QV4; ++q) {
            ulonglong2 p = hcol[q * H2W];
            ull s = vcol[q * HB2W];
#pragma unroll
            for (int rr = 0; rr < 4; ++rr) {
                int j = q - rr;
                if (j >= 0 && j < K) {
                    ffma2(a3[rr], gp[j], p.x);
                    ffma2(a4[rr], gp[j], p.y);
                    ffma2(a2[rr], gp[j], s);
                }
            }
        }
#pragma unroll
        for (int rr = 0; rr < 4; ++rr) {
            float m3p, m3t, m4p, m4t, s2p, s2t;
            unpack2(a3[rr], m3p, m3t);
            unpack2(a4[rr], m4p, m4t);
            unpack2(a2[rr], s2p, s2t);
            float mp, mt;
            unpack2(ms[(org + rr + R) * MSW + (ocx + R)], mp, mt);
            float vp = fmaxf(s2p - mp * mp, 1e-8f);
            float vt = fmaxf(s2t - mt * mt, 1e-8f);
            float sdp = sqrtf(vp), sdt = sqrtf(vt);
            float skp = __fdividef(m3p, sdp * sdp * sdp + 1e-8f);
            float skt = __fdividef(m3t, sdt * sdt * sdt + 1e-8f);
            float kup = __fdividef(m4p, vp * vp + 1e-8f);
            float kut = __fdividef(m4t, vt * vt + 1e-8f);
            acc += fabsf(mp - mt)
                 + fabsf(vp - vt)
                 + 0.5f   * fabsf(skp - skt)
                 + 0.001f * fabsf(kup - kut);
        }
    }

    // ---- block reduction, atomic accumulate ----
#pragma unroll
    for (int off = 16; off > 0; off >>= 1)
        acc += __shfl_xor_sync(0xffffffffu, acc, off);
    if ((tid & 31) == 0) wsum[tid >> 5] = acc;
    __syncthreads();
    if (tid < 32) {
        float v = (tid < NTHREADS / 32) ? wsum[tid] : 0.0f;
#pragma unroll
        for (int off = 16; off > 0; off >>= 1)
            v += __shfl_xor_sync(0xffffffffu, v, off);
        if (tid == 0) atomicAdd(&g_acc, (double)v);
    }
}

extern "C" void kernel_launch(void* const* d_in, const int* in_sizes, int n_in,
                              void* d_out, int out_size) {
    const float* pred = (const float*)d_in[0];
    const float* tgt  = (const float*)d_in[1];
    float* out = (float*)d_out;

    const int npix = in_sizes[0];                 // 16*3*512*512
    const int planes = npix / (IMG_H * IMG_W);    // 48

    dim3 grid(IMG_W / TILE, IMG_H / TILE, planes);

    cudaFuncSetAttribute(stat_loss_kernel<3>, cudaFuncAttributeMaxDynamicSharedMemorySize,
                         smem_total(3));
    cudaFuncSetAttribute(stat_loss_kernel<5>, cudaFuncAttributeMaxDynamicSharedMemorySize,
                         smem_total(5));
    cudaFuncSetAttribute(stat_loss_kernel<7>, cudaFuncAttributeMaxDynamicSharedMemorySize,
                         smem_total(7));

    init_acc_kernel<<<1, 1>>>();
    stat_loss_kernel<3><<<grid, NTHREADS, smem_total(3)>>>(pred, tgt);
    stat_loss_kernel<5><<<grid, NTHREADS, smem_total(5)>>>(pred, tgt);
    stat_loss_kernel<7><<<grid, NTHREADS, smem_total(7)>>>(pred, tgt);

    const double scale = 1.0 / (12.0 * (double)npix);
    finalize_kernel<<<1, 1>>>(out, scale);
}

// round 8
// speedup vs baseline: 1.3616x; 1.2809x over previous
#include <cuda_runtime.h>
#include <math.h>

typedef unsigned long long ull;

#define IMG 512
#define BW  288     // threads per block = columns per strip
#define CH  128     // output rows per chunk

__device__ double g_acc;

__global__ void init_acc_kernel() { g_acc = 0.0; }

__global__ void finalize_kernel(float* out, double scale) {
    out[0] = (float)(g_acc * scale);
}

// ---- f32x2 packed helpers ----
__device__ __forceinline__ ull pack2(float lo, float hi) {
    ull r;
    asm("mov.b64 %0, {%1, %2};" : "=l"(r) : "f"(lo), "f"(hi));
    return r;
}
__device__ __forceinline__ void unpack2(ull v, float& lo, float& hi) {
    asm("mov.b64 {%0, %1}, %2;" : "=f"(lo), "=f"(hi) : "l"(v));
}
__device__ __forceinline__ void ffma2(ull& d, ull a, ull b) {
    asm("fma.rn.f32x2 %0, %1, %2, %0;" : "+l"(d) : "l"(a), "l"(b));
}
__device__ __forceinline__ ull fma2v(ull a, ull b, ull c) {   // a*b + c
    ull d;
    asm("fma.rn.f32x2 %0, %1, %2, %3;" : "=l"(d) : "l"(a), "l"(b), "l"(c));
    return d;
}
__device__ __forceinline__ ull mul2(ull a, ull b) {
    ull d;
    asm("mul.rn.f32x2 %0, %1, %2;" : "=l"(d) : "l"(a), "l"(b));
    return d;
}

// Streaming register-systolic kernel. Each thread owns one column.
// Per row iteration:
//   x[r] exchanged via smem ring -> h1, hs2 (horizontal convs)
//   mean/S2 systolic accumulators complete row m = r-R
//   xc[m] = x[m] - mean[m] (x from register ring), written to smem NEXT iter
//   hc3/hc4 convolve the xc row written this iter (row r-R-1)
//   m3/m4 systolic complete output row o = r-2R-1 -> loss terms
template <int K>
__global__ __launch_bounds__(BW)
void stat_stream_kernel(const float* __restrict__ pred,
                        const float* __restrict__ tgt)
{
    constexpr int R    = K / 2;
    constexpr int UWB  = BW - 6 * R;          // useful output columns per block
    constexpr int U    = R + 2;               // ring depth / inner unroll
    constexpr int NRAW = CH + 4 * R + 1;      // rows streamed per chunk
    constexpr int NITER = ((NRAW + U - 1) / U) * U;

    __shared__ __align__(16) ull sbuf[2 * U * BW + 16];  // pad|xcbuf|xbuf|pad
    __shared__ float wsum[BW / 32];
    ull* xcbuf = sbuf + 8;
    ull* xbuf  = xcbuf + U * BW;

    const int tid = threadIdx.x;
    const int c0  = blockIdx.y * CH;
    const int col = blockIdx.x * UWB - 3 * R + tid;
    const bool incol = (unsigned)col < (unsigned)IMG;
    const bool uc = (tid >= 3 * R) && (tid < 3 * R + UWB) && incol;
    const size_t plane = (size_t)blockIdx.z * (size_t)(IMG * IMG);

    // normalized 1D gaussian, packed into both f32x2 lanes
    ull gp[K];
    {
        const float sigma = (float)K / 6.0f;
        const float inv2s2 = 1.0f / (2.0f * sigma * sigma);
        float gt[K];
        float s = 0.0f;
#pragma unroll
        for (int j = 0; j < K; ++j) {
            float c = (float)(j - K / 2);
            gt[j] = expf(-c * c * inv2s2);
            s += gt[j];
        }
        float inv = 1.0f / s;
#pragma unroll
        for (int j = 0; j < K; ++j) { float w = gt[j] * inv; gp[j] = pack2(w, w); }
    }
    const ull NEG1 = pack2(-1.0f, -1.0f);

    // systolic partials (K-1 pending each) + register rings
    ull Am[K - 1], As[K - 1], A3[K - 1], A4[K - 1];
#pragma unroll
    for (int i = 0; i < K - 1; ++i) { Am[i] = 0; As[i] = 0; A3[i] = 0; A4[i] = 0; }
    ull xr[U], i3r[U], i4r[U];
#pragma unroll
    for (int i = 0; i < U; ++i) { xr[i] = 0; i3r[i] = 0; i4r[i] = 0; }

    const int r0 = c0 - 2 * R;
    const float* pp = pred + plane + (long long)r0 * IMG + col;
    const float* pt = tgt  + plane + (long long)r0 * IMG + col;

    // preload x row r0
    ull xv;
    {
        float a = 0.0f, b = 0.0f;
        if (incol && ((unsigned)r0 < (unsigned)IMG)) { a = pp[0]; b = pt[0]; }
        xv = pack2(a, b);
        pp += IMG; pt += IMG;
    }
    ull xc_pend = 0ull;
    float acc = 0.0f;

#pragma unroll 1
    for (int p0 = 0; p0 < NITER; p0 += U) {
#pragma unroll
        for (int u = 0; u < U; ++u) {
            const int p = p0 + u;

            // publish current x row and the pending xc row (row r-R-1)
            xbuf [u * BW + tid] = xv;
            xcbuf[u * BW + tid] = xc_pend;

            // prefetch next x row (overlaps barrier + compute)
            ull xv_n;
            {
                int rn = r0 + p + 1;
                float a = 0.0f, b = 0.0f;
                if (incol && ((unsigned)rn < (unsigned)IMG)) { a = pp[0]; b = pt[0]; }
                xv_n = pack2(a, b);
                pp += IMG; pt += IMG;
            }
            __syncthreads();

            // ---- level-1 horizontal convs: h1 = conv(x), hs2 = conv(x^2) ----
            ull h1 = 0ull, hs2 = 0ull;
            {
                const ull* xb = xbuf + u * BW + (tid - R);
#pragma unroll
                for (int j = 0; j < K; ++j) {
                    ull t = xb[j];
                    ffma2(h1, gp[j], t);
                    ull t2 = mul2(t, t);
                    ffma2(hs2, gp[j], t2);
                }
            }

            // ---- mean/S2 vertical systolic: completes row m = r-R ----
            ull meanc = Am[0]; ffma2(meanc, gp[K - 1], h1);
            ull S2c   = As[0]; ffma2(S2c,   gp[K - 1], hs2);
#pragma unroll
            for (int i = 0; i < K - 2; ++i) {
                ull a = Am[i + 1]; ffma2(a, gp[K - 2 - i], h1);  Am[i] = a;
                ull b = As[i + 1]; ffma2(b, gp[K - 2 - i], hs2); As[i] = b;
            }
            Am[K - 2] = mul2(gp[0], h1);
            As[K - 2] = mul2(gp[0], hs2);

            // ---- xc for row m (x from register ring); zero outside image ----
            {
                ull xm = xr[(u + U - R) % U];
                int m = r0 + p - R;
                ull xcn = fma2v(meanc, NEG1, xm);
                bool mimg = incol && ((unsigned)m < (unsigned)IMG);
                xc_pend = mimg ? xcn : 0ull;
            }
            xr[u] = xv;

            // ---- features at m: |dmean|+|dvar|, inverse rings for skew/kurt ----
            const int m_idx = p - 3 * R;          // m - c0  (uniform across block)
            if ((unsigned)m_idx < (unsigned)CH) {
                float mp, mt, sp, st;
                unpack2(meanc, mp, mt);
                unpack2(S2c,   sp, st);
                float vp = fmaxf(fmaf(-mp, mp, sp), 1e-8f);
                float vt = fmaxf(fmaf(-mt, mt, st), 1e-8f);
                if (uc) acc += fabsf(mp - mt) + fabsf(vp - vt);
                float sdp = sqrtf(vp), sdt = sqrtf(vt);
                float i3p = __fdividef(1.0f, fmaf(sdp, vp, 1e-8f));  // 1/(sd^3+eps)
                float i3t = __fdividef(1.0f, fmaf(sdt, vt, 1e-8f));
                float i4p = __fdividef(1.0f, fmaf(vp, vp, 1e-8f));   // 1/(var^2+eps)
                float i4t = __fdividef(1.0f, fmaf(vt, vt, 1e-8f));
                i3r[u] = pack2(i3p, i3t);
                i4r[u] = pack2(i4p, i4t);
            }

            // ---- level-2 horizontal convs on xc row r-R-1 ----
            ull hc3 = 0ull, hc4 = 0ull;
            {
                const ull* cb = xcbuf + u * BW + (tid - R);
#pragma unroll
                for (int j = 0; j < K; ++j) {
                    ull s  = cb[j];
                    ull s2 = mul2(s, s);
                    ull c3 = mul2(s2, s);
                    ull c4 = mul2(s2, s2);
                    ffma2(hc3, gp[j], c3);
                    ffma2(hc4, gp[j], c4);
                }
            }

            // ---- m3/m4 vertical systolic: completes output row o = r-2R-1 ----
            ull m3c = A3[0]; ffma2(m3c, gp[K - 1], hc3);
            ull m4c = A4[0]; ffma2(m4c, gp[K - 1], hc4);
#pragma unroll
            for (int i = 0; i < K - 2; ++i) {
                ull a = A3[i + 1]; ffma2(a, gp[K - 2 - i], hc3); A3[i] = a;
                ull b = A4[i + 1]; ffma2(b, gp[K - 2 - i], hc4); A4[i] = b;
            }
            A3[K - 2] = mul2(gp[0], hc3);
            A4[K - 2] = mul2(gp[0], hc4);

            const int o_idx = p - (4 * R + 1);    // o - c0 (uniform)
            if ((unsigned)o_idx < (unsigned)CH) {
                float m3p, m3t, m4p, m4t;
                unpack2(m3c, m3p, m3t);
                unpack2(m4c, m4p, m4t);
                float i3p, i3t, i4p, i4t;
                unpack2(i3r[(u + 2 * U - (R + 1)) % U], i3p, i3t);
                unpack2(i4r[(u + 2 * U - (R + 1)) % U], i4p, i4t);
                if (uc) {
                    acc += 0.5f   * fabsf(m3p * i3p - m3t * i3t)
                         + 0.001f * fabsf(m4p * i4p - m4t * i4t);
                }
            }

            xv = xv_n;
        }
    }

    // ---- block reduction, atomic accumulate ----
#pragma unroll
    for (int off = 16; off > 0; off >>= 1)
        acc += __shfl_xor_sync(0xffffffffu, acc, off);
    if ((tid & 31) == 0) wsum[tid >> 5] = acc;
    __syncthreads();
    if (tid < 32) {
        float v = (tid < BW / 32) ? wsum[tid] : 0.0f;
#pragma unroll
        for (int off = 16; off > 0; off >>= 1)
            v += __shfl_xor_sync(0xffffffffu, v, off);
        if (tid == 0) atomicAdd(&g_acc, (double)v);
    }
}

extern "C" void kernel_launch(void* const* d_in, const int* in_sizes, int n_in,
                              void* d_out, int out_size) {
    const float* pred = (const float*)d_in[0];
    const float* tgt  = (const float*)d_in[1];
    float* out = (float*)d_out;

    const int npix = in_sizes[0];               // 16*3*512*512
    const int planes = npix / (IMG * IMG);      // 48

    dim3 grid(2, IMG / CH, planes);             // 2 col strips x 4 chunks x planes

    init_acc_kernel<<<1, 1>>>();
    stat_stream_kernel<3><<<grid, BW>>>(pred, tgt);
    stat_stream_kernel<5><<<grid, BW>>>(pred, tgt);
    stat_stream_kernel<7><<<grid, BW>>>(pred, tgt);

    const double scale = 1.0 / (12.0 * (double)npix);
    finalize_kernel<<<1, 1>>>(out, scale);
}

// round 9
// speedup vs baseline: 1.5670x; 1.1509x over previous
#include <cuda_runtime.h>
#include <math.h>

typedef unsigned long long ull;

#define IMG 512
#define BW  288     // threads per block = columns per strip
#define CH  64      // output rows per chunk

__device__ double g_acc;

__global__ void init_acc_kernel() { g_acc = 0.0; }

__global__ void finalize_kernel(float* out, double scale) {
    out[0] = (float)(g_acc * scale);
}

// ---- f32x2 packed helpers ----
__device__ __forceinline__ ull pack2(float lo, float hi) {
    ull r;
    asm("mov.b64 %0, {%1, %2};" : "=l"(r) : "f"(lo), "f"(hi));
    return r;
}
__device__ __forceinline__ void unpack2(ull v, float& lo, float& hi) {
    asm("mov.b64 {%0, %1}, %2;" : "=f"(lo), "=f"(hi) : "l"(v));
}
__device__ __forceinline__ void ffma2(ull& d, ull a, ull b) {
    asm("fma.rn.f32x2 %0, %1, %2, %0;" : "+l"(d) : "l"(a), "l"(b));
}
__device__ __forceinline__ ull fma2v(ull a, ull b, ull c) {   // a*b + c
    ull d;
    asm("fma.rn.f32x2 %0, %1, %2, %3;" : "=l"(d) : "l"(a), "l"(b), "l"(c));
    return d;
}
__device__ __forceinline__ ull mul2(ull a, ull b) {
    ull d;
    asm("mul.rn.f32x2 %0, %1, %2;" : "=l"(d) : "l"(a), "l"(b));
    return d;
}

// Streaming register-systolic kernel. Each thread owns one column.
// Per row iteration:
//   x[r] exchanged via smem ring -> h1, hs2 (horizontal convs)
//   mean/S2 systolic accumulators complete row m = r-R
//   xc[m] = x[m] - mean[m] (x from register ring), published NEXT iter
//   hc3/hc4 convolve the xc row published this iter (row r-R-1)
//   m3/m4 systolic complete output row o = r-2R-1 -> loss terms
template <int K, int MINB>
__global__ __launch_bounds__(BW, MINB)
void stat_stream_kernel(const float* __restrict__ pred,
                        const float* __restrict__ tgt)
{
    constexpr int R    = K / 2;
    constexpr int UWB  = BW - 6 * R;          // useful output columns per block
    constexpr int U    = R + 2;               // ring depth / inner unroll
    constexpr int NRAW = CH + 4 * R + 1;      // rows streamed per chunk
    constexpr int NITER = ((NRAW + U - 1) / U) * U;

    __shared__ __align__(16) ull sbuf[2 * U * BW + 16];  // pad|xcbuf|xbuf|pad
    __shared__ float wsum[BW / 32];
    ull* xcbuf = sbuf + 8;
    ull* xbuf  = xcbuf + U * BW;

    const int tid = threadIdx.x;
    const int c0  = blockIdx.y * CH;
    const int col = blockIdx.x * UWB - 3 * R + tid;
    const bool incol = (unsigned)col < (unsigned)IMG;
    const bool uc = (tid >= 3 * R) && (tid < 3 * R + UWB) && incol;
    const size_t plane = (size_t)blockIdx.z * (size_t)(IMG * IMG);

    // normalized 1D gaussian, packed into both f32x2 lanes
    ull gp[K];
    {
        const float sigma = (float)K / 6.0f;
        const float inv2s2 = 1.0f / (2.0f * sigma * sigma);
        float gt[K];
        float s = 0.0f;
#pragma unroll
        for (int j = 0; j < K; ++j) {
            float c = (float)(j - K / 2);
            gt[j] = expf(-c * c * inv2s2);
            s += gt[j];
        }
        float inv = 1.0f / s;
#pragma unroll
        for (int j = 0; j < K; ++j) { float w = gt[j] * inv; gp[j] = pack2(w, w); }
    }
    const ull NEG1 = pack2(-1.0f, -1.0f);

    // systolic partials (K-1 pending each) + register rings
    ull Am[K - 1], As[K - 1], A3[K - 1], A4[K - 1];
#pragma unroll
    for (int i = 0; i < K - 1; ++i) { Am[i] = 0; As[i] = 0; A3[i] = 0; A4[i] = 0; }
    ull xr[U], i3r[U], i4r[U];
#pragma unroll
    for (int i = 0; i < U; ++i) { xr[i] = 0; i3r[i] = 0; i4r[i] = 0; }

    const int r0 = c0 - 2 * R;
    const float* pp = pred + plane + (long long)r0 * IMG + col;
    const float* pt = tgt  + plane + (long long)r0 * IMG + col;

    // preload x row r0
    ull xv;
    {
        float a = 0.0f, b = 0.0f;
        if (incol && ((unsigned)r0 < (unsigned)IMG)) { a = pp[0]; b = pt[0]; }
        xv = pack2(a, b);
        pp += IMG; pt += IMG;
    }
    ull xc_pend = 0ull;
    float acc = 0.0f;

#pragma unroll 1
    for (int p0 = 0; p0 < NITER; p0 += U) {
#pragma unroll
        for (int u = 0; u < U; ++u) {
            const int p = p0 + u;

            // publish current x row and the pending xc row (row r-R-1)
            xbuf [u * BW + tid] = xv;
            xcbuf[u * BW + tid] = xc_pend;

            // prefetch next x row (overlaps barrier + compute)
            ull xv_n;
            {
                int rn = r0 + p + 1;
                float a = 0.0f, b = 0.0f;
                if (incol && ((unsigned)rn < (unsigned)IMG)) { a = pp[0]; b = pt[0]; }
                xv_n = pack2(a, b);
                pp += IMG; pt += IMG;
            }
            __syncthreads();

            // ---- level-1 horizontal convs: h1 = conv(x), hs2 = conv(x^2) ----
            ull h1 = 0ull, hs2 = 0ull;
            {
                const ull* xb = xbuf + u * BW + (tid - R);
#pragma unroll
                for (int j = 0; j < K; ++j) {
                    ull t = xb[j];
                    ffma2(h1, gp[j], t);
                    ull t2 = mul2(t, t);
                    ffma2(hs2, gp[j], t2);
                }
            }

            // ---- mean/S2 vertical systolic: completes row m = r-R ----
            ull meanc = Am[0]; ffma2(meanc, gp[K - 1], h1);
            ull S2c   = As[0]; ffma2(S2c,   gp[K - 1], hs2);
#pragma unroll
            for (int i = 0; i < K - 2; ++i) {
                ull a = Am[i + 1]; ffma2(a, gp[K - 2 - i], h1);  Am[i] = a;
                ull b = As[i + 1]; ffma2(b, gp[K - 2 - i], hs2); As[i] = b;
            }
            Am[K - 2] = mul2(gp[0], h1);
            As[K - 2] = mul2(gp[0], hs2);

            // ---- xc for row m (x from register ring); zero outside image ----
            {
                ull xm = xr[(u + U - R) % U];
                int m = r0 + p - R;
                ull xcn = fma2v(meanc, NEG1, xm);
                bool mimg = incol && ((unsigned)m < (unsigned)IMG);
                xc_pend = mimg ? xcn : 0ull;
            }
            xr[u] = xv;

            // ---- features at m: |dmean|+|dvar|, inverse rings for skew/kurt ----
            const int m_idx = p - 3 * R;          // m - c0  (uniform across block)
            if ((unsigned)m_idx < (unsigned)CH) {
                float mp, mt, sp, st;
                unpack2(meanc, mp, mt);
                unpack2(S2c,   sp, st);
                float vp = fmaxf(fmaf(-mp, mp, sp), 1e-8f);
                float vt = fmaxf(fmaf(-mt, mt, st), 1e-8f);
                if (uc) acc += fabsf(mp - mt) + fabsf(vp - vt);
                float sdp = sqrtf(vp), sdt = sqrtf(vt);
                float i3p = __fdividef(1.0f, fmaf(sdp, vp, 1e-8f));  // 1/(sd^3+eps)
                float i3t = __fdividef(1.0f, fmaf(sdt, vt, 1e-8f));
                float i4p = __fdividef(1.0f, fmaf(vp, vp, 1e-8f));   // 1/(var^2+eps)
                float i4t = __fdividef(1.0f, fmaf(vt, vt, 1e-8f));
                i3r[u] = pack2(i3p, i3t);
                i4r[u] = pack2(i4p, i4t);
            }

            // ---- level-2 horizontal convs on xc row r-R-1 ----
            ull hc3 = 0ull, hc4 = 0ull;
            {
                const ull* cb = xcbuf + u * BW + (tid - R);
#pragma unroll
                for (int j = 0; j < K; ++j) {
                    ull s  = cb[j];
                    ull s2 = mul2(s, s);
                    ull c3 = mul2(s2, s);
                    ull c4 = mul2(s2, s2);
                    ffma2(hc3, gp[j], c3);
                    ffma2(hc4, gp[j], c4);
                }
            }

            // ---- m3/m4 vertical systolic: completes output row o = r-2R-1 ----
            ull m3c = A3[0]; ffma2(m3c, gp[K - 1], hc3);
            ull m4c = A4[0]; ffma2(m4c, gp[K - 1], hc4);
#pragma unroll
            for (int i = 0; i < K - 2; ++i) {
                ull a = A3[i + 1]; ffma2(a, gp[K - 2 - i], hc3); A3[i] = a;
                ull b = A4[i + 1]; ffma2(b, gp[K - 2 - i], hc4); A4[i] = b;
            }
            A3[K - 2] = mul2(gp[0], hc3);
            A4[K - 2] = mul2(gp[0], hc4);

            const int o_idx = p - (4 * R + 1);    // o - c0 (uniform)
            if ((unsigned)o_idx < (unsigned)CH) {
                float m3p, m3t, m4p, m4t;
                unpack2(m3c, m3p, m3t);
                unpack2(m4c, m4p, m4t);
                float i3p, i3t, i4p, i4t;
                unpack2(i3r[(u + 2 * U - (R + 1)) % U], i3p, i3t);
                unpack2(i4r[(u + 2 * U - (R + 1)) % U], i4p, i4t);
                if (uc) {
                    acc += 0.5f   * fabsf(m3p * i3p - m3t * i3t)
                         + 0.001f * fabsf(m4p * i4p - m4t * i4t);
                }
            }

            xv = xv_n;
        }
    }

    // ---- block reduction, atomic accumulate ----
#pragma unroll
    for (int off = 16; off > 0; off >>= 1)
        acc += __shfl_xor_sync(0xffffffffu, acc, off);
    if ((tid & 31) == 0) wsum[tid >> 5] = acc;
    __syncthreads();
    if (tid < 32) {
        float v = (tid < BW / 32) ? wsum[tid] : 0.0f;
#pragma unroll
        for (int off = 16; off > 0; off >>= 1)
            v += __shfl_xor_sync(0xffffffffu, v, off);
        if (tid == 0) atomicAdd(&g_acc, (double)v);
    }
}

extern "C" void kernel_launch(void* const* d_in, const int* in_sizes, int n_in,
                              void* d_out, int out_size) {
    const float* pred = (const float*)d_in[0];
    const float* tgt  = (const float*)d_in[1];
    float* out = (float*)d_out;

    const int npix = in_sizes[0];               // 16*3*512*512
    const int planes = npix / (IMG * IMG);      // 48

    dim3 grid(2, IMG / CH, planes);             // 2 col strips x 8 chunks x planes

    init_acc_kernel<<<1, 1>>>();
    stat_stream_kernel<3, 3><<<grid, BW>>>(pred, tgt);
    stat_stream_kernel<5, 2><<<grid, BW>>>(pred, tgt);
    stat_stream_kernel<7, 2><<<grid, BW>>>(pred, tgt);

    const double scale = 1.0 / (12.0 * (double)npix);
    finalize_kernel<<<1, 1>>>(out, scale);
}